// round 1
// baseline (speedup 1.0000x reference)
#include <cuda_runtime.h>
#include <math.h>

#define B 64
#define T 512
#define D 1024

// Scratch (static __device__ arrays — allocation-free per harness rules)
__device__ float g_hT[2][D * B];   // hidden state, TRANSPOSED: [k][b], double-buffered
__device__ float g_UT[D * D];      // U_w transposed: UT[k][n] = U_w[n][k]

// ---------------- zero initial hidden state ----------------
__global__ void zero_h0() {
    int i = blockIdx.x * blockDim.x + threadIdx.x;
    if (i < D * B) g_hT[0][i] = 0.f;
}

// ---------------- transpose U_w -> g_UT ----------------
__global__ void transpose_U(const float* __restrict__ U) {
    __shared__ float tile[32][33];
    int k = blockIdx.x * 32 + threadIdx.x;
    int n = blockIdx.y * 32 + threadIdx.y;
    #pragma unroll
    for (int i = 0; i < 32; i += 8)
        tile[threadIdx.y + i][threadIdx.x] = U[(size_t)(n + i) * D + k];
    __syncthreads();
    int kout = blockIdx.x * 32 + threadIdx.y;
    int nout = blockIdx.y * 32 + threadIdx.x;
    #pragma unroll
    for (int i = 0; i < 32; i += 8)
        g_UT[(size_t)(kout + i) * D + nout] = tile[threadIdx.x][threadIdx.y + i];
}

// ---------------- wx = X @ W^T + W_b  (written into d_out resultEmbs region) ----------------
// M = B*T = 32768, N = D = 1024, K = D = 1024. BM=BN=64, BK=16, 256 thr, 4x4/thread.
__global__ void __launch_bounds__(256) gemm_wx(const float* __restrict__ X,
                                               const float* __restrict__ W,
                                               const float* __restrict__ Wb,
                                               float* __restrict__ C) {
    __shared__ float As[16][68];   // [k][m], padded (68*4 bytes keeps 16B alignment)
    __shared__ float Bs[16][68];   // [k][n]
    const int m0 = blockIdx.y * 64;
    const int n0 = blockIdx.x * 64;
    const int tx = threadIdx.x & 15;   // n-thread
    const int ty = threadIdx.x >> 4;   // m-thread
    const int lk = threadIdx.x & 15;   // load: k index
    const int lr = threadIdx.x >> 4;   // load: row index 0..15

    float acc[4][4] = {};
    for (int k0 = 0; k0 < D; k0 += 16) {
        #pragma unroll
        for (int i = 0; i < 4; ++i) {
            As[lk][lr + 16 * i] = X[(size_t)(m0 + lr + 16 * i) * D + k0 + lk];
            Bs[lk][lr + 16 * i] = W[(size_t)(n0 + lr + 16 * i) * D + k0 + lk];
        }
        __syncthreads();
        #pragma unroll
        for (int kk = 0; kk < 16; ++kk) {
            float4 a = *(const float4*)&As[kk][ty * 4];
            float4 b = *(const float4*)&Bs[kk][tx * 4];
            acc[0][0] += a.x * b.x; acc[0][1] += a.x * b.y; acc[0][2] += a.x * b.z; acc[0][3] += a.x * b.w;
            acc[1][0] += a.y * b.x; acc[1][1] += a.y * b.y; acc[1][2] += a.y * b.z; acc[1][3] += a.y * b.w;
            acc[2][0] += a.z * b.x; acc[2][1] += a.z * b.y; acc[2][2] += a.z * b.z; acc[2][3] += a.z * b.w;
            acc[3][0] += a.w * b.x; acc[3][1] += a.w * b.y; acc[3][2] += a.w * b.z; acc[3][3] += a.w * b.w;
        }
        __syncthreads();
    }
    float4 bv = *(const float4*)&Wb[n0 + tx * 4];
    #pragma unroll
    for (int mi = 0; mi < 4; ++mi) {
        size_t m = (size_t)(m0 + ty * 4 + mi);
        float4 v = make_float4(acc[mi][0] + bv.x, acc[mi][1] + bv.y,
                               acc[mi][2] + bv.z, acc[mi][3] + bv.w);
        *(float4*)&C[m * D + n0 + tx * 4] = v;
    }
}

// ---------------- one recurrent step ----------------
// h_new[b,n] = tanh(wx[b,t,n] + sum_k h[b,k]*U[n,k] + Ub[n] + bias[n])
// grid = 128 blocks (8 n-columns each, all 64 batches), 256 threads = 8 warps.
// Warp w owns K-chunk [w*128, w*128+128), computes the full 64x8 tile partial
// with a 4x4 register tile over k-major (transposed) h and U, then warps
// reduce through smem. Epilogue fuses wx-add + bias + tanh, writes the output
// row in place and the next transposed hidden state.
__global__ void __launch_bounds__(256) rnn_step(float* __restrict__ out,
                                                const float* __restrict__ Ub,
                                                const float* __restrict__ bias,
                                                int t, int parity) {
    const float* __restrict__ hin = g_hT[parity];
    float* __restrict__ hout      = g_hT[parity ^ 1];

    const int warp = threadIdx.x >> 5;     // 0..7 -> k-chunk
    const int lane = threadIdx.x & 31;
    const int nt   = lane >> 4;            // 0..1  (n sub-tile)
    const int bt   = lane & 15;            // 0..15 (b sub-tile)
    const int n0   = blockIdx.x * 8;

    float acc[4][4] = {};
    const float4* hp = (const float4*)(hin + warp * 128 * B) + bt;               // row = 16 float4
    const float4* up = (const float4*)(g_UT + (size_t)warp * 128 * D + n0) + nt; // row = 256 float4

    #pragma unroll 4
    for (int kk = 0; kk < 128; ++kk) {
        float4 h = hp[kk * 16];
        float4 u = up[kk * 256];
        acc[0][0] += h.x * u.x; acc[0][1] += h.x * u.y; acc[0][2] += h.x * u.z; acc[0][3] += h.x * u.w;
        acc[1][0] += h.y * u.x; acc[1][1] += h.y * u.y; acc[1][2] += h.y * u.z; acc[1][3] += h.y * u.w;
        acc[2][0] += h.z * u.x; acc[2][1] += h.z * u.y; acc[2][2] += h.z * u.z; acc[2][3] += h.z * u.w;
        acc[3][0] += h.w * u.x; acc[3][1] += h.w * u.y; acc[3][2] += h.w * u.z; acc[3][3] += h.w * u.w;
    }

    __shared__ float red[8][8][68];   // [warp][n_local][b], padded: conflict-free, 16B-aligned rows
    #pragma unroll
    for (int ni = 0; ni < 4; ++ni) {
        float4 v = make_float4(acc[0][ni], acc[1][ni], acc[2][ni], acc[3][ni]);
        *(float4*)&red[warp][nt * 4 + ni][bt * 4] = v;
    }
    __syncthreads();

    #pragma unroll
    for (int i = threadIdx.x; i < 512; i += 256) {
        int b  = i >> 3;
        int nl = i & 7;
        float s = 0.f;
        #pragma unroll
        for (int w = 0; w < 8; ++w) s += red[w][nl][b];
        int n = n0 + nl;
        size_t oidx = (size_t)b * (T * D) + (size_t)t * D + n;
        float z  = out[oidx] + s + Ub[n] + bias[n];
        float hn = tanhf(z);
        out[oidx]         = hn;      // resultEmbs[b,t,n] (overwrites wx in place)
        hout[n * B + b]   = hn;      // transposed hidden state for step t+1
    }
}

// ---------------- copy final hidden state into hx region ----------------
__global__ void copy_hx(float* __restrict__ out) {
    int i = blockIdx.x * blockDim.x + threadIdx.x;   // i = b*D + n
    if (i < B * D) {
        int b = i >> 10, n = i & (D - 1);
        out[(size_t)B * T * D + i] = out[(size_t)b * T * D + (size_t)(T - 1) * D + n];
    }
}

extern "C" void kernel_launch(void* const* d_in, const int* in_sizes, int n_in,
                              void* d_out, int out_size) {
    const float* x    = (const float*)d_in[0];
    const float* Ww   = (const float*)d_in[1];
    const float* Wb   = (const float*)d_in[2];
    const float* Uw   = (const float*)d_in[3];
    const float* Ub   = (const float*)d_in[4];
    const float* bias = (const float*)d_in[5];
    float* out = (float*)d_out;

    zero_h0<<<(B * D + 255) / 256, 256>>>();
    transpose_U<<<dim3(D / 32, D / 32), dim3(32, 8)>>>(Uw);
    gemm_wx<<<dim3(D / 64, (B * T) / 64), 256>>>(x, Ww, Wb, out);

    for (int t = 0; t < T; ++t)
        rnn_step<<<128, 256>>>(out, Ub, bias, t, t & 1);

    copy_hx<<<(B * D + 255) / 256, 256>>>(out);
}

// round 2
// speedup vs baseline: 3.5114x; 3.5114x over previous
#include <cuda_runtime.h>
#include <math.h>

#define B 64
#define T 512
#define D 1024
#define NBLK 128          // persistent grid size (<= 148 SMs -> co-resident)

// Scratch (static __device__ arrays — allocation-free per harness rules)
__device__ float g_hT[2][D * B];   // hidden state, TRANSPOSED: [k][b], double-buffered
__device__ float g_UT[D * D];      // U_w transposed: UT[k][n] = U_w[n][k]
__device__ unsigned g_ctr;         // grid-barrier monotonic counter

// ---------------- init: zero h0, reset barrier counter ----------------
__global__ void zero_h0() {
    int i = blockIdx.x * blockDim.x + threadIdx.x;
    if (i < D * B) g_hT[0][i] = 0.f;
    if (i == 0) g_ctr = 0;
}

// ---------------- transpose U_w -> g_UT ----------------
__global__ void transpose_U(const float* __restrict__ U) {
    __shared__ float tile[32][33];
    int k = blockIdx.x * 32 + threadIdx.x;
    int n = blockIdx.y * 32 + threadIdx.y;
    #pragma unroll
    for (int i = 0; i < 32; i += 8)
        tile[threadIdx.y + i][threadIdx.x] = U[(size_t)(n + i) * D + k];
    __syncthreads();
    int kout = blockIdx.x * 32 + threadIdx.y;
    int nout = blockIdx.y * 32 + threadIdx.x;
    #pragma unroll
    for (int i = 0; i < 32; i += 8)
        g_UT[(size_t)(kout + i) * D + nout] = tile[threadIdx.x][threadIdx.y + i];
}

// ---------------- wx = X @ W^T + W_b  (written into d_out resultEmbs region) ----------------
__global__ void __launch_bounds__(256) gemm_wx(const float* __restrict__ X,
                                               const float* __restrict__ W,
                                               const float* __restrict__ Wb,
                                               float* __restrict__ C) {
    __shared__ float As[16][68];
    __shared__ float Bs[16][68];
    const int m0 = blockIdx.y * 64;
    const int n0 = blockIdx.x * 64;
    const int tx = threadIdx.x & 15;
    const int ty = threadIdx.x >> 4;
    const int lk = threadIdx.x & 15;
    const int lr = threadIdx.x >> 4;

    float acc[4][4] = {};
    for (int k0 = 0; k0 < D; k0 += 16) {
        #pragma unroll
        for (int i = 0; i < 4; ++i) {
            As[lk][lr + 16 * i] = X[(size_t)(m0 + lr + 16 * i) * D + k0 + lk];
            Bs[lk][lr + 16 * i] = W[(size_t)(n0 + lr + 16 * i) * D + k0 + lk];
        }
        __syncthreads();
        #pragma unroll
        for (int kk = 0; kk < 16; ++kk) {
            float4 a = *(const float4*)&As[kk][ty * 4];
            float4 b = *(const float4*)&Bs[kk][tx * 4];
            acc[0][0] += a.x * b.x; acc[0][1] += a.x * b.y; acc[0][2] += a.x * b.z; acc[0][3] += a.x * b.w;
            acc[1][0] += a.y * b.x; acc[1][1] += a.y * b.y; acc[1][2] += a.y * b.z; acc[1][3] += a.y * b.w;
            acc[2][0] += a.z * b.x; acc[2][1] += a.z * b.y; acc[2][2] += a.z * b.z; acc[2][3] += a.z * b.w;
            acc[3][0] += a.w * b.x; acc[3][1] += a.w * b.y; acc[3][2] += a.w * b.z; acc[3][3] += a.w * b.w;
        }
        __syncthreads();
    }
    float4 bv = *(const float4*)&Wb[n0 + tx * 4];
    #pragma unroll
    for (int mi = 0; mi < 4; ++mi) {
        size_t m = (size_t)(m0 + ty * 4 + mi);
        float4 v = make_float4(acc[mi][0] + bv.x, acc[mi][1] + bv.y,
                               acc[mi][2] + bv.z, acc[mi][3] + bv.w);
        *(float4*)&C[m * D + n0 + tx * 4] = v;
    }
}

// ---------------- persistent recurrence: all 512 steps in ONE kernel ----------------
// 128 blocks x 1024 threads (32 warps). Block owns 8 n-columns.
// Warp w owns K-chunk [w*32, w*32+32): 4x4 register tile over transposed h (__ldcg,
// L2-coherent, keeps L1 for U) and transposed U (__ldg, 32KB slice stays hot in L1
// for all 512 steps). Two-phase smem reduction (32 -> 16 -> final), fused
// wx-add + bias + tanh epilogue, software grid barrier between steps.
__global__ void __launch_bounds__(1024, 1) rnn_persistent(float* __restrict__ out,
                                                          const float* __restrict__ Ub,
                                                          const float* __restrict__ bias) {
    const int tid  = threadIdx.x;
    const int warp = tid >> 5;          // 0..31 -> k-chunk
    const int lane = tid & 31;
    const int nt   = lane >> 4;         // 0..1  (n sub-tile)
    const int bt   = lane & 15;         // 0..15 (b sub-tile)
    const int n0   = blockIdx.x * 8;

    __shared__ float red[16][8][68];    // [warp-pair][n_local][b], padded

    // U pointer for this warp/lane (never changes across steps)
    const float4* up = (const float4*)(g_UT + (size_t)warp * 32 * D + n0) + nt;  // stride 256 f4/k

    // epilogue constants (threads 0..511)
    const int eb = tid >> 3;            // batch 0..63
    const int en = tid & 7;             // n_local 0..7
    float cconst = 0.f;
    size_t obase = 0;
    if (tid < 512) {
        int n = n0 + en;
        cconst = Ub[n] + bias[n];
        obase  = (size_t)eb * (T * D) + n;
    }

    for (int t = 0; t < T; ++t) {
        const float* hin = g_hT[t & 1];
        float* hout      = g_hT[(t + 1) & 1];

        const float4* hp = (const float4*)(hin + warp * 32 * B) + bt;  // stride 16 f4/k

        float acc[4][4] = {};
        #pragma unroll 8
        for (int kk = 0; kk < 32; ++kk) {
            float4 h = __ldcg(&hp[kk * 16]);     // L2 only (coherent across SMs)
            float4 u = __ldg(&up[kk * 256]);     // L1-resident across steps
            acc[0][0] += h.x * u.x; acc[0][1] += h.x * u.y; acc[0][2] += h.x * u.z; acc[0][3] += h.x * u.w;
            acc[1][0] += h.y * u.x; acc[1][1] += h.y * u.y; acc[1][2] += h.y * u.z; acc[1][3] += h.y * u.w;
            acc[2][0] += h.z * u.x; acc[2][1] += h.z * u.y; acc[2][2] += h.z * u.z; acc[2][3] += h.z * u.w;
            acc[3][0] += h.w * u.x; acc[3][1] += h.w * u.y; acc[3][2] += h.w * u.z; acc[3][3] += h.w * u.w;
        }

        // two-phase reduction: warps 16..31 store, warps 0..15 accumulate in
        if (warp >= 16) {
            #pragma unroll
            for (int ni = 0; ni < 4; ++ni)
                *(float4*)&red[warp - 16][nt * 4 + ni][bt * 4] =
                    make_float4(acc[0][ni], acc[1][ni], acc[2][ni], acc[3][ni]);
        }
        __syncthreads();
        if (warp < 16) {
            #pragma unroll
            for (int ni = 0; ni < 4; ++ni) {
                float4 v = *(const float4*)&red[warp][nt * 4 + ni][bt * 4];
                v.x += acc[0][ni]; v.y += acc[1][ni]; v.z += acc[2][ni]; v.w += acc[3][ni];
                *(float4*)&red[warp][nt * 4 + ni][bt * 4] = v;
            }
        }
        __syncthreads();

        // epilogue: 512 outputs (64 b x 8 n)
        if (tid < 512) {
            float s = 0.f;
            #pragma unroll
            for (int w = 0; w < 16; ++w) s += red[w][en][eb];
            size_t oidx = obase + (size_t)t * D;
            float z  = __ldcg(&out[oidx]) + s + cconst;   // wx was pre-stored in out
            float hn = tanhf(z);
            out[oidx] = hn;                                // resultEmbs[b,t,n]
            hout[(n0 + en) * B + eb] = hn;                 // transposed h for next step
        }

        // ---- grid barrier (sense-free monotonic counter) ----
        __threadfence();
        __syncthreads();
        if (tid == 0) {
            atomicAdd(&g_ctr, 1u);
            unsigned target = (unsigned)(t + 1) * NBLK;
            while (*(volatile unsigned*)&g_ctr < target) { }
            __threadfence();
        }
        __syncthreads();
    }
}

// ---------------- copy final hidden state into hx region ----------------
__global__ void copy_hx(float* __restrict__ out) {
    int i = blockIdx.x * blockDim.x + threadIdx.x;   // i = b*D + n
    if (i < B * D) {
        int b = i >> 10, n = i & (D - 1);
        out[(size_t)B * T * D + i] = out[(size_t)b * T * D + (size_t)(T - 1) * D + n];
    }
}

extern "C" void kernel_launch(void* const* d_in, const int* in_sizes, int n_in,
                              void* d_out, int out_size) {
    const float* x    = (const float*)d_in[0];
    const float* Ww   = (const float*)d_in[1];
    const float* Wb   = (const float*)d_in[2];
    const float* Uw   = (const float*)d_in[3];
    const float* Ub   = (const float*)d_in[4];
    const float* bias = (const float*)d_in[5];
    float* out = (float*)d_out;

    zero_h0<<<(B * D + 255) / 256, 256>>>();
    transpose_U<<<dim3(D / 32, D / 32), dim3(32, 8)>>>(Uw);
    gemm_wx<<<dim3(D / 64, (B * T) / 64), 256>>>(x, Ww, Wb, out);
    rnn_persistent<<<NBLK, 1024>>>(out, Ub, bias);
    copy_hx<<<(B * D + 255) / 256, 256>>>(out);
}

// round 4
// speedup vs baseline: 4.3442x; 1.2372x over previous
#include <cuda_runtime.h>
#include <cuda_bf16.h>
#include <mma.h>
#include <math.h>
#include <stdint.h>

using namespace nvcuda;

#define B 64
#define T 512
#define D 1024
#define NBLK 128          // persistent grid size (<= 148 SMs -> co-resident)

#define KK 3072           // concatenated K: [hi | lo | hi] x [hi | hi | lo]
#define BM 128
#define BN 128
#define BK 32
#define NK (KK / BK)      // 96
#define LDT 40            // padded smem row stride (elements): 32 + 8 -> 80B
#define STAGE_A (BM * LDT * 2)          // 10240 B
#define AB_STAGES 3
#define SMEM_B_OFF (AB_STAGES * STAGE_A)          // 30720
#define SMEM_BIAS_OFF (2 * AB_STAGES * STAGE_A)   // 61440
#define GEMM_SMEM (SMEM_BIAS_OFF + 16 * BN * 4)   // 69632

// ---------------- scratch (static __device__ arrays; allocation-free) ----------------
__device__ float g_hT[2][D * B];                       // hidden state, transposed [k][b]
__device__ float g_UT[D * D];                          // U_w transposed
__device__ unsigned g_ctr;                             // grid-barrier counter
__device__ __nv_bfloat16 g_xs[(size_t)B * T * KK];     // x split, K-concat [hi|lo|hi] (192MB)
__device__ __nv_bfloat16 g_ws[(size_t)D * KK];         // W split, K-concat [hi|hi|lo] (6MB)

// ---------------- small helpers ----------------
__device__ __forceinline__ uint32_t smem_u32(const void* p) {
    uint32_t a;
    asm("{ .reg .u64 t; cvta.to.shared.u64 t, %1; cvt.u32.u64 %0, t; }" : "=r"(a) : "l"(p));
    return a;
}
__device__ __forceinline__ void cp_async16(uint32_t dst, const void* src) {
    asm volatile("cp.async.cg.shared.global [%0], [%1], 16;" :: "r"(dst), "l"(src) : "memory");
}

// ---------------- init: zero h0, reset barrier counter ----------------
__global__ void zero_h0() {
    int i = blockIdx.x * blockDim.x + threadIdx.x;
    if (i < D * B) g_hT[0][i] = 0.f;
    if (i == 0) g_ctr = 0;
}

// ---------------- fp32 -> bf16 hi/lo split, K-concat layout ----------------
__global__ void split_x(const float* __restrict__ s) {
    size_t i = (size_t)blockIdx.x * blockDim.x + threadIdx.x;   // one float4 per thread
    float4 v = ((const float4*)s)[i];
    size_t e = i * 4;
    size_t m = e >> 10;
    int    k = (int)(e & 1023);
    __nv_bfloat16 hx = __float2bfloat16(v.x), hy = __float2bfloat16(v.y);
    __nv_bfloat16 hz = __float2bfloat16(v.z), hw = __float2bfloat16(v.w);
    __nv_bfloat162 h01(hx, hy), h23(hz, hw);
    __nv_bfloat162 l01(__float2bfloat16(v.x - __bfloat162float(hx)),
                       __float2bfloat16(v.y - __bfloat162float(hy)));
    __nv_bfloat162 l23(__float2bfloat16(v.z - __bfloat162float(hz)),
                       __float2bfloat16(v.w - __bfloat162float(hw)));
    __nv_bfloat16* row = g_xs + m * KK;
    *(__nv_bfloat162*)(row + k)             = h01;  *(__nv_bfloat162*)(row + k + 2)         = h23;
    *(__nv_bfloat162*)(row + D + k)         = l01;  *(__nv_bfloat162*)(row + D + k + 2)     = l23;
    *(__nv_bfloat162*)(row + 2 * D + k)     = h01;  *(__nv_bfloat162*)(row + 2 * D + k + 2) = h23;
}
__global__ void split_w(const float* __restrict__ s) {
    size_t i = (size_t)blockIdx.x * blockDim.x + threadIdx.x;
    float4 v = ((const float4*)s)[i];
    size_t e = i * 4;
    size_t n = e >> 10;
    int    k = (int)(e & 1023);
    __nv_bfloat16 hx = __float2bfloat16(v.x), hy = __float2bfloat16(v.y);
    __nv_bfloat16 hz = __float2bfloat16(v.z), hw = __float2bfloat16(v.w);
    __nv_bfloat162 h01(hx, hy), h23(hz, hw);
    __nv_bfloat162 l01(__float2bfloat16(v.x - __bfloat162float(hx)),
                       __float2bfloat16(v.y - __bfloat162float(hy)));
    __nv_bfloat162 l23(__float2bfloat16(v.z - __bfloat162float(hz)),
                       __float2bfloat16(v.w - __bfloat162float(hw)));
    __nv_bfloat16* row = g_ws + n * KK;
    *(__nv_bfloat162*)(row + k)             = h01;  *(__nv_bfloat162*)(row + k + 2)         = h23;
    *(__nv_bfloat162*)(row + D + k)         = h01;  *(__nv_bfloat162*)(row + D + k + 2)     = h23;
    *(__nv_bfloat162*)(row + 2 * D + k)     = l01;  *(__nv_bfloat162*)(row + 2 * D + k + 2) = l23;
}

// ---------------- transpose U_w -> g_UT (for the fp32 recurrence) ----------------
__global__ void transpose_U(const float* __restrict__ U) {
    __shared__ float tile[32][33];
    int k = blockIdx.x * 32 + threadIdx.x;
    int n = blockIdx.y * 32 + threadIdx.y;
    #pragma unroll
    for (int i = 0; i < 32; i += 8)
        tile[threadIdx.y + i][threadIdx.x] = U[(size_t)(n + i) * D + k];
    __syncthreads();
    int kout = blockIdx.x * 32 + threadIdx.y;
    int nout = blockIdx.y * 32 + threadIdx.x;
    #pragma unroll
    for (int i = 0; i < 32; i += 8)
        g_UT[(size_t)(kout + i) * D + nout] = tile[threadIdx.x][threadIdx.y + i];
}

// ================= wx = x @ W^T + Wb via wmma (HMMA), K'=3072 =================
__device__ __forceinline__ void fill_stage(uint32_t sb, int s, int m0, int n0, int k0, int tid) {
    uint32_t sa = sb + s * STAGE_A;
    uint32_t sbb = sb + SMEM_B_OFF + s * STAGE_A;
    #pragma unroll
    for (int j = 0; j < 2; ++j) {
        int idx = tid + j * 256;           // 0..511
        int r = idx >> 2, c = idx & 3;     // row 0..127, 16B chunk 0..3
        cp_async16(sa + r * (LDT * 2) + c * 16, g_xs + (size_t)(m0 + r) * KK + k0 + c * 8);
    }
    #pragma unroll
    for (int j = 0; j < 2; ++j) {
        int idx = tid + j * 256;
        int r = idx >> 2, c = idx & 3;
        cp_async16(sbb + r * (LDT * 2) + c * 16, g_ws + (size_t)(n0 + r) * KK + k0 + c * 8);
    }
    asm volatile("cp.async.commit_group;" ::: "memory");
}

__global__ void __launch_bounds__(256) gemm_wx_mma(float* __restrict__ out,
                                                   const float* __restrict__ Wb) {
    extern __shared__ char smem[];
    uint32_t sb = smem_u32(smem);
    float* biasT = (float*)(smem + SMEM_BIAS_OFF);   // 16 x BN, every row = Wb slice
    const int tid = threadIdx.x, warp = tid >> 5;
    const int wm = warp & 3, wn = warp >> 2;         // 4 x 2 warp grid, 32x64 warp tiles
    const int n0 = blockIdx.x * BN, m0 = blockIdx.y * BM;

    for (int i = tid; i < 16 * BN; i += 256) biasT[i] = Wb[n0 + (i & (BN - 1))];
    __syncthreads();

    wmma::fragment<wmma::accumulator, 16, 16, 16, float> c[2][4];
    #pragma unroll
    for (int i = 0; i < 2; ++i)
        #pragma unroll
        for (int j = 0; j < 4; ++j)
            wmma::load_matrix_sync(c[i][j], biasT + wn * 64 + j * 16, BN, wmma::mem_row_major);

    fill_stage(sb, 0, m0, n0, 0, tid);
    fill_stage(sb, 1, m0, n0, BK, tid);

    int rs = 0, ws = 2;
    for (int ks = 0; ks < NK; ++ks) {
        asm volatile("cp.async.wait_group 1;" ::: "memory");
        __syncthreads();

        const __nv_bfloat16* As = (const __nv_bfloat16*)(smem + rs * STAGE_A);
        const __nv_bfloat16* Bs = (const __nv_bfloat16*)(smem + SMEM_B_OFF + rs * STAGE_A);
        #pragma unroll
        for (int kk = 0; kk < 2; ++kk) {
            wmma::fragment<wmma::matrix_a, 16, 16, 16, __nv_bfloat16, wmma::row_major> a[2];
            wmma::fragment<wmma::matrix_b, 16, 16, 16, __nv_bfloat16, wmma::col_major> b[4];
            #pragma unroll
            for (int i = 0; i < 2; ++i)
                wmma::load_matrix_sync(a[i], As + (wm * 32 + i * 16) * LDT + kk * 16, LDT);
            #pragma unroll
            for (int j = 0; j < 4; ++j)
                wmma::load_matrix_sync(b[j], Bs + (wn * 64 + j * 16) * LDT + kk * 16, LDT);
            #pragma unroll
            for (int i = 0; i < 2; ++i)
                #pragma unroll
                for (int j = 0; j < 4; ++j)
                    wmma::mma_sync(c[i][j], a[i], b[j], c[i][j]);
        }

        if (ks + 2 < NK) fill_stage(sb, ws, m0, n0, (ks + 2) * BK, tid);
        else asm volatile("cp.async.commit_group;" ::: "memory");
        rs = (rs == 2) ? 0 : rs + 1;
        ws = (ws == 2) ? 0 : ws + 1;
    }

    #pragma unroll
    for (int i = 0; i < 2; ++i)
        #pragma unroll
        for (int j = 0; j < 4; ++j)
            wmma::store_matrix_sync(out + (size_t)(m0 + wm * 32 + i * 16) * D + n0 + wn * 64 + j * 16,
                                    c[i][j], D, wmma::mem_row_major);
}

// ---------------- persistent recurrence: all 512 steps in ONE kernel ----------------
__global__ void __launch_bounds__(1024, 1) rnn_persistent(float* __restrict__ out,
                                                          const float* __restrict__ Ub,
                                                          const float* __restrict__ bias) {
    const int tid  = threadIdx.x;
    const int warp = tid >> 5;
    const int lane = tid & 31;
    const int nt   = lane >> 4;
    const int bt   = lane & 15;
    const int n0   = blockIdx.x * 8;

    __shared__ float red[16][8][68];

    const float4* up = (const float4*)(g_UT + (size_t)warp * 32 * D + n0) + nt;

    const int eb = tid >> 3;
    const int en = tid & 7;
    float cconst = 0.f;
    size_t obase = 0;
    if (tid < 512) {
        int n = n0 + en;
        cconst = Ub[n] + bias[n];
        obase  = (size_t)eb * (T * D) + n;
    }

    for (int t = 0; t < T; ++t) {
        const float* hin = g_hT[t & 1];
        float* hout      = g_hT[(t + 1) & 1];
        const float4* hp = (const float4*)(hin + warp * 32 * B) + bt;

        float acc[4][4] = {};
        #pragma unroll 8
        for (int kk = 0; kk < 32; ++kk) {
            float4 h = __ldcg(&hp[kk * 16]);
            float4 u = __ldg(&up[kk * 256]);
            acc[0][0] += h.x * u.x; acc[0][1] += h.x * u.y; acc[0][2] += h.x * u.z; acc[0][3] += h.x * u.w;
            acc[1][0] += h.y * u.x; acc[1][1] += h.y * u.y; acc[1][2] += h.y * u.z; acc[1][3] += h.y * u.w;
            acc[2][0] += h.z * u.x; acc[2][1] += h.z * u.y; acc[2][2] += h.z * u.z; acc[2][3] += h.z * u.w;
            acc[3][0] += h.w * u.x; acc[3][1] += h.w * u.y; acc[3][2] += h.w * u.z; acc[3][3] += h.w * u.w;
        }

        if (warp >= 16) {
            #pragma unroll
            for (int ni = 0; ni < 4; ++ni)
                *(float4*)&red[warp - 16][nt * 4 + ni][bt * 4] =
                    make_float4(acc[0][ni], acc[1][ni], acc[2][ni], acc[3][ni]);
        }
        __syncthreads();
        if (warp < 16) {
            #pragma unroll
            for (int ni = 0; ni < 4; ++ni) {
                float4 v = *(const float4*)&red[warp][nt * 4 + ni][bt * 4];
                v.x += acc[0][ni]; v.y += acc[1][ni]; v.z += acc[2][ni]; v.w += acc[3][ni];
                *(float4*)&red[warp][nt * 4 + ni][bt * 4] = v;
            }
        }
        __syncthreads();

        if (tid < 512) {
            float s = 0.f;
            #pragma unroll
            for (int w = 0; w < 16; ++w) s += red[w][en][eb];
            size_t oidx = obase + (size_t)t * D;
            float z  = __ldcg(&out[oidx]) + s + cconst;
            float hn = tanhf(z);
            out[oidx] = hn;
            hout[(n0 + en) * B + eb] = hn;
        }

        __threadfence();
        __syncthreads();
        if (tid == 0) {
            atomicAdd(&g_ctr, 1u);
            unsigned target = (unsigned)(t + 1) * NBLK;
            while (*(volatile unsigned*)&g_ctr < target) { }
            __threadfence();
        }
        __syncthreads();
    }
}

// ---------------- copy final hidden state into hx region ----------------
__global__ void copy_hx(float* __restrict__ out) {
    int i = blockIdx.x * blockDim.x + threadIdx.x;
    if (i < B * D) {
        int b = i >> 10, n = i & (D - 1);
        out[(size_t)B * T * D + i] = out[(size_t)b * T * D + (size_t)(T - 1) * D + n];
    }
}

extern "C" void kernel_launch(void* const* d_in, const int* in_sizes, int n_in,
                              void* d_out, int out_size) {
    const float* x    = (const float*)d_in[0];
    const float* Ww   = (const float*)d_in[1];
    const float* Wb   = (const float*)d_in[2];
    const float* Uw   = (const float*)d_in[3];
    const float* Ub   = (const float*)d_in[4];
    const float* bias = (const float*)d_in[5];
    float* out = (float*)d_out;

    cudaFuncSetAttribute(gemm_wx_mma, cudaFuncAttributeMaxDynamicSharedMemorySize, GEMM_SMEM);

    zero_h0<<<(B * D + 255) / 256, 256>>>();
    split_x<<<((size_t)B * T * D / 4) / 256, 256>>>(x);
    split_w<<<(D * D / 4) / 256, 256>>>(Ww);
    transpose_U<<<dim3(D / 32, D / 32), dim3(32, 8)>>>(Uw);
    gemm_wx_mma<<<dim3(D / BN, (B * T) / BM), 256, GEMM_SMEM>>>(out, Wb);
    rnn_persistent<<<NBLK, 1024>>>(out, Ub, bias);
    copy_hx<<<(B * D + 255) / 256, 256>>>(out);
}